// round 1
// baseline (speedup 1.0000x reference)
#include <cuda_runtime.h>
#include <math.h>

// Problem constants
#define BB      16
#define NCG     256
#define NATOMS  1024
#define KNN     32
#define KF      128
#define DEPTH   3

#define CGS_PER_CTA 2
#define MROWS  (CGS_PER_CTA * KNN)   // 64 rows per CTA
#define THREADS 256
#define PAD     68                   // smem row stride in floats (16B-aligned: 68*4=272)

// -------- scratch (no allocs allowed) --------
__device__ float g_G[BB * KF * 3];        // G[b][k][n]
__device__ float g_S[BB * 3];             // S[b][n]
__device__ float g_dx[BB * NATOMS * 3];   // dx_recon
__device__ float g_cgoff[BB * NCG * 3];   // cg_offset

// ---------------- zero scratch ----------------
__global__ void zero_kernel() {
    const int n1 = BB * KF * 3;
    const int n2 = BB * 3;
    const int n3 = BB * NCG * 3;
    const int total = n1 + n2 + n3;
    for (int i = blockIdx.x * blockDim.x + threadIdx.x; i < total;
         i += gridDim.x * blockDim.x) {
        if (i < n1)            g_G[i] = 0.f;
        else if (i < n1 + n2)  g_S[i - n1] = 0.f;
        else                   g_cgoff[i - n1 - n2] = 0.f;
    }
}

// ---------------- fused MLP chain ----------------
// smem layout (floats):
//   bufA [KF][PAD]  (transposed activations: [feature][row])
//   bufB [KF][PAD]
//   dv   [MROWS][4]
//   dist [MROWS]
//   Ws   [16][KF]   (weight k-tile)
#define SMEM_FLOATS (2 * KF * PAD + MROWS * 4 + MROWS + 16 * KF)
#define SMEM_BYTES  (SMEM_FLOATS * 4)

// One GEMM: Ys[c][r] = (relu?)( sum_k Xs[k][r] * W[k][c] + bias[c] )
// 64 rows x 128 cols, 256 threads: warp = row-group(8 rows), lane = col-group(4 cols)
__device__ __forceinline__ void gemm64(const float* __restrict__ Xs,
                                       float* __restrict__ Ys,
                                       float* __restrict__ Ws,
                                       const float* __restrict__ W,
                                       const float* __restrict__ bias,
                                       bool relu) {
    const int t   = threadIdx.x;
    const int c0  = (t & 31) * 4;   // lanes cover all 128 cols
    const int r0  = (t >> 5) * 8;   // warp id = row group

    float acc[8][4];
    #pragma unroll
    for (int i = 0; i < 8; i++)
        #pragma unroll
        for (int j = 0; j < 4; j++) acc[i][j] = 0.f;

    for (int kt = 0; kt < KF; kt += 16) {
        __syncthreads();   // protect Ws (and on kt==0, order prior buffer writes)
        {   // stage 16x128 weight rows: 512 float4, 2 per thread
            const float4* src = (const float4*)(W + kt * KF);
            float4* dst = (float4*)Ws;
            dst[t]       = src[t];
            dst[t + 256] = src[t + 256];
        }
        __syncthreads();

        #pragma unroll
        for (int kk = 0; kk < 16; kk++) {
            const int k = kt + kk;
            float4 w  = *(const float4*)(Ws + kk * KF + c0);
            float4 a0 = *(const float4*)(Xs + k * PAD + r0);
            float4 a1 = *(const float4*)(Xs + k * PAD + r0 + 4);
            float a[8] = {a0.x, a0.y, a0.z, a0.w, a1.x, a1.y, a1.z, a1.w};
            #pragma unroll
            for (int i = 0; i < 8; i++) {
                acc[i][0] = fmaf(a[i], w.x, acc[i][0]);
                acc[i][1] = fmaf(a[i], w.y, acc[i][1]);
                acc[i][2] = fmaf(a[i], w.z, acc[i][2]);
                acc[i][3] = fmaf(a[i], w.w, acc[i][3]);
            }
        }
    }

    float4 bv = *(const float4*)(bias + c0);
    float bb[4] = {bv.x, bv.y, bv.z, bv.w};
    #pragma unroll
    for (int j = 0; j < 4; j++) {
        float o[8];
        #pragma unroll
        for (int i = 0; i < 8; i++) {
            float v = acc[i][j] + bb[j];
            if (relu) v = fmaxf(v, 0.f);
            o[i] = v;
        }
        *(float4*)(Ys + (c0 + j) * PAD + r0)     = make_float4(o[0], o[1], o[2], o[3]);
        *(float4*)(Ys + (c0 + j) * PAD + r0 + 4) = make_float4(o[4], o[5], o[6], o[7]);
    }
}

// h = upd + mean over KNN rows within each cg group (in place, transposed buf)
__device__ __forceinline__ void add_mean(float* __restrict__ Ys) {
    const int t   = threadIdx.x;         // 256 = 128 feats * 2 groups
    const int c   = t >> 1;
    const int grp = t & 1;
    float* p = Ys + c * PAD + grp * KNN;
    float s = 0.f;
    #pragma unroll
    for (int i = 0; i < KNN; i++) s += p[i];
    s *= (1.0f / KNN);
    #pragma unroll
    for (int i = 0; i < KNN; i++) p[i] += s;
}

extern __shared__ float smem[];

__global__ __launch_bounds__(THREADS, 2)
void fused_kernel(const float* __restrict__ cg_xyz,
                  const float* __restrict__ mlp_W1, const float* __restrict__ mlp_b1,
                  const float* __restrict__ mlp_W2, const float* __restrict__ mlp_b2,
                  const float* __restrict__ upd_W1, const float* __restrict__ upd_b1,
                  const float* __restrict__ upd_W2, const float* __restrict__ upd_b2,
                  const float* __restrict__ dec_W1, const float* __restrict__ dec_b1) {
    float* bufA = smem;
    float* bufB = bufA + KF * PAD;
    float* dv   = bufB + KF * PAD;            // [MROWS][4]
    float* dist = dv + MROWS * 4;             // [MROWS]
    float* Ws   = dist + MROWS;               // [16][KF]

    const int t   = threadIdx.x;
    const int blk = blockIdx.x;               // B * NCG / CGS_PER_CTA = 2048
    const int b   = blk >> 7;                 // / (NCG/CGS_PER_CTA=128)
    const int cg0 = (blk & 127) * CGS_PER_CTA;

    // Phase 0: dist_vec + dist for our 64 rows (row = cg_local*32 + j; neighbor = cg 1+j)
    if (t < MROWS) {
        const int cg = cg0 + (t / KNN);
        const int j  = t % KNN;
        const float* pj = cg_xyz + (size_t)(b * NCG + 1 + j) * 3;
        const float* pc = cg_xyz + (size_t)(b * NCG + cg) * 3;
        float d0 = pj[0] - pc[0], d1 = pj[1] - pc[1], d2 = pj[2] - pc[2];
        dv[t * 4 + 0] = d0; dv[t * 4 + 1] = d1; dv[t * 4 + 2] = d2;
        dist[t] = sqrtf(d0 * d0 + d1 * d1 + d2 * d2);
    }
    __syncthreads();

    // RBF expansion into bufA (transposed [k][r])
    const float delta = 10.0f / 127.0f;
    const float coeff = -0.5f / (delta * delta);
    for (int idx = t; idx < KF * MROWS; idx += THREADS) {
        const int k = idx / MROWS, r = idx % MROWS;
        const float x = dist[r] - (float)k * delta;
        bufA[k * PAD + r] = expf(coeff * x * x);
    }

    // 3 depths x (2 mlp GEMMs + mean + 2 upd GEMMs)
    float* X = bufA;
    float* Y = bufB;
    for (int d = 0; d < DEPTH; d++) {
        const size_t wo = (size_t)d * KF * KF;
        const size_t bo = (size_t)d * KF;
        gemm64(X, Y, Ws, mlp_W1 + wo, mlp_b1 + bo, true);
        gemm64(Y, X, Ws, mlp_W2 + wo, mlp_b2 + bo, false);
        __syncthreads();
        add_mean(X);
        gemm64(X, Y, Ws, upd_W1 + wo, upd_b1 + bo, true);
        gemm64(Y, X, Ws, upd_W2 + wo, upd_b2 + bo, false);
    }
    // decoder first layer
    gemm64(X, Y, Ws, dec_W1, dec_b1, true);   // Y = F (transposed)
    __syncthreads();

    // G[b][k][n] += sum_r F[k][r] * dv[r][n];  S[b][n] += sum_r dv[r][n]
    for (int p = t; p < KF * 3; p += THREADS) {
        const int k = p / 3, n = p % 3;
        const float* Fk = Y + k * PAD;
        float s = 0.f;
        #pragma unroll 8
        for (int r = 0; r < MROWS; r++) s = fmaf(Fk[r], dv[r * 4 + n], s);
        atomicAdd(&g_G[(b * KF + k) * 3 + n], s);
    }
    if (t < 3) {
        float s = 0.f;
        for (int r = 0; r < MROWS; r++) s += dv[r * 4 + t];
        atomicAdd(&g_S[b * 3 + t], s);
    }
}

// ---------------- dx_recon = G @ dec_W2 + dec_b2 * S ----------------
__global__ void dx_kernel(const float* __restrict__ dec_W2,
                          const float* __restrict__ dec_b2) {
    __shared__ float Gs[KF * 3];
    __shared__ float Ss[3];
    const int b = blockIdx.x >> 2;
    const int o = ((blockIdx.x & 3) << 8) + threadIdx.x;
    for (int i = threadIdx.x; i < KF * 3; i += 256) Gs[i] = g_G[b * KF * 3 + i];
    if (threadIdx.x < 3) Ss[threadIdx.x] = g_S[b * 3 + threadIdx.x];
    __syncthreads();
    float d0 = 0.f, d1 = 0.f, d2 = 0.f;
    #pragma unroll 4
    for (int k = 0; k < KF; k++) {
        const float w = dec_W2[k * NATOMS + o];
        d0 = fmaf(Gs[k * 3 + 0], w, d0);
        d1 = fmaf(Gs[k * 3 + 1], w, d1);
        d2 = fmaf(Gs[k * 3 + 2], w, d2);
    }
    const float bb = dec_b2[o];
    d0 += bb * Ss[0]; d1 += bb * Ss[1]; d2 += bb * Ss[2];
    float* p = g_dx + (size_t)(b * NATOMS + o) * 3;
    p[0] = d0; p[1] = d1; p[2] = d2;
}

// ---------------- cg_offset[b][j][n] = sum_o dx[b][o][n] * assign_norm[b][o][j] ----------------
__global__ void cgoff_kernel(const float* __restrict__ assign_norm) {
    __shared__ float dxs[256 * 3];
    const int b  = blockIdx.x >> 2;
    const int oc = blockIdx.x & 3;            // chunk of 256 atoms
    const int j  = threadIdx.x;
    const int obase = oc * 256;
    for (int i = threadIdx.x; i < 256 * 3; i += 256)
        dxs[i] = g_dx[(size_t)(b * NATOMS + obase) * 3 + i];
    __syncthreads();
    float a0 = 0.f, a1 = 0.f, a2 = 0.f;
    for (int oo = 0; oo < 256; oo++) {
        const float an = assign_norm[((size_t)b * NATOMS + obase + oo) * NCG + j];
        a0 = fmaf(an, dxs[oo * 3 + 0], a0);
        a1 = fmaf(an, dxs[oo * 3 + 1], a1);
        a2 = fmaf(an, dxs[oo * 3 + 2], a2);
    }
    atomicAdd(&g_cgoff[(b * NCG + j) * 3 + 0], a0);
    atomicAdd(&g_cgoff[(b * NCG + j) * 3 + 1], a1);
    atomicAdd(&g_cgoff[(b * NCG + j) * 3 + 2], a2);
}

// ---------------- xyz_recon = cg_xyz[idx] - cg_offset[idx] + dx ----------------
__global__ void recon_kernel(const float* __restrict__ cg_xyz,
                             const int* __restrict__ assign_idx,
                             float* __restrict__ out) {
    const int i = blockIdx.x * blockDim.x + threadIdx.x;  // b*NATOMS + o
    if (i >= BB * NATOMS) return;
    const int b = i >> 10;
    const int o = i & 1023;
    const int ai = assign_idx[o];
    const float* cx = cg_xyz + (size_t)(b * NCG + ai) * 3;
    const float* co = g_cgoff + (size_t)(b * NCG + ai) * 3;
    const float* dx = g_dx + (size_t)i * 3;
    float* po = out + (size_t)BB * NATOMS * NCG + (size_t)BB * NATOMS * 3 + (size_t)i * 3;
    po[0] = cx[0] - co[0] + dx[0];
    po[1] = cx[1] - co[1] + dx[1];
    po[2] = cx[2] - co[2] + dx[2];
}

// ---------------- launch ----------------
extern "C" void kernel_launch(void* const* d_in, const int* in_sizes, int n_in,
                              void* d_out, int out_size) {
    const float* soft_assign = (const float*)d_in[0];
    const float* xyz         = (const float*)d_in[1];
    const float* cg_xyz      = (const float*)d_in[2];
    const float* assign_norm = (const float*)d_in[3];
    const int*   assign_idx  = (const int*)d_in[4];
    const float* mlp_W1 = (const float*)d_in[5];
    const float* mlp_b1 = (const float*)d_in[6];
    const float* mlp_W2 = (const float*)d_in[7];
    const float* mlp_b2 = (const float*)d_in[8];
    const float* upd_W1 = (const float*)d_in[9];
    const float* upd_b1 = (const float*)d_in[10];
    const float* upd_W2 = (const float*)d_in[11];
    const float* upd_b2 = (const float*)d_in[12];
    const float* dec_W1 = (const float*)d_in[13];
    const float* dec_b1 = (const float*)d_in[14];
    const float* dec_W2 = (const float*)d_in[15];
    const float* dec_b2 = (const float*)d_in[16];

    float* out = (float*)d_out;

    // passthrough copies: soft_assign, xyz
    cudaMemcpyAsync(out, soft_assign, (size_t)BB * NATOMS * NCG * sizeof(float),
                    cudaMemcpyDeviceToDevice);
    cudaMemcpyAsync(out + (size_t)BB * NATOMS * NCG, xyz,
                    (size_t)BB * NATOMS * 3 * sizeof(float), cudaMemcpyDeviceToDevice);

    zero_kernel<<<32, 256>>>();

    cudaFuncSetAttribute(fused_kernel, cudaFuncAttributeMaxDynamicSharedMemorySize,
                         SMEM_BYTES);
    fused_kernel<<<BB * NCG / CGS_PER_CTA, THREADS, SMEM_BYTES>>>(
        cg_xyz, mlp_W1, mlp_b1, mlp_W2, mlp_b2,
        upd_W1, upd_b1, upd_W2, upd_b2, dec_W1, dec_b1);

    dx_kernel<<<BB * 4, 256>>>(dec_W2, dec_b2);
    cgoff_kernel<<<BB * 4, 256>>>(assign_norm);
    recon_kernel<<<(BB * NATOMS + 255) / 256, 256>>>(cg_xyz, assign_idx, out);
}

// round 2
// speedup vs baseline: 1.1158x; 1.1158x over previous
#include <cuda_runtime.h>
#include <math.h>
#include <stdint.h>

// Problem constants
#define BB      16
#define NCG     256
#define NATOMS  1024
#define KNN     32
#define KF      128
#define DEPTH   3

#define CGS_PER_CTA 2
#define MROWS  (CGS_PER_CTA * KNN)   // 64 rows per CTA
#define THREADS 256
#define PAD     68                   // smem row stride in floats (16B-aligned)

// -------- scratch (no allocs allowed) --------
__device__ float g_G[BB * KF * 3];        // G[b][k][n]
__device__ float g_S[BB * 3];             // S[b][n]
__device__ float g_dx[BB * NATOMS * 3];   // dx_recon
__device__ float g_cgoff[BB * NCG * 3];   // cg_offset

// ---------------- packed f32x2 helpers ----------------
__device__ __forceinline__ void fma_f32x2(unsigned long long& d,
                                          unsigned long long a,
                                          unsigned long long b,
                                          unsigned long long c) {
    asm("fma.rn.f32x2 %0, %1, %2, %3;" : "=l"(d) : "l"(a), "l"(b), "l"(c));
}
__device__ __forceinline__ unsigned long long dup_f32(float x) {
    unsigned long long r;
    unsigned int u = __float_as_uint(x);
    asm("mov.b64 %0, {%1, %1};" : "=l"(r) : "r"(u));
    return r;
}
__device__ __forceinline__ void unpack_f32x2(float& lo, float& hi,
                                             unsigned long long v) {
    unsigned int a, b;
    asm("mov.b64 {%0, %1}, %2;" : "=r"(a), "=r"(b) : "l"(v));
    lo = __uint_as_float(a);
    hi = __uint_as_float(b);
}

// ---------------- cp.async helpers ----------------
__device__ __forceinline__ void cp_async16(uint32_t smem_addr, const void* gptr) {
    asm volatile("cp.async.cg.shared.global [%0], [%1], 16;"
                 :: "r"(smem_addr), "l"(gptr));
}
__device__ __forceinline__ void cp_async_commit() {
    asm volatile("cp.async.commit_group;");
}
template <int N>
__device__ __forceinline__ void cp_async_wait() {
    asm volatile("cp.async.wait_group %0;" :: "n"(N));
}

// ---------------- zero scratch ----------------
__global__ void zero_kernel() {
    const int n1 = BB * KF * 3;
    const int n2 = BB * 3;
    const int n3 = BB * NCG * 3;
    const int total = n1 + n2 + n3;
    for (int i = blockIdx.x * blockDim.x + threadIdx.x; i < total;
         i += gridDim.x * blockDim.x) {
        if (i < n1)            g_G[i] = 0.f;
        else if (i < n1 + n2)  g_S[i - n1] = 0.f;
        else                   g_cgoff[i - n1 - n2] = 0.f;
    }
}

// smem layout (floats):
//   bufA [KF][PAD], bufB [KF][PAD], dv [MROWS][4], dist [MROWS], Ws [2][16][KF]
#define SMEM_FLOATS (2 * KF * PAD + MROWS * 4 + MROWS + 2 * 16 * KF)
#define SMEM_BYTES  (SMEM_FLOATS * 4)

// One GEMM: Ys[c][r] = (relu?)( sum_k Xs[k][r] * W[k][c] + bias[c] )
// 64 rows x 128 cols, 256 threads: warp = 8-row group, lane = 4-col group.
// Inner math in packed f32x2 (row pairs). Weights double-buffered via cp.async.
__device__ __forceinline__ void gemm64(const float* __restrict__ Xs,
                                       float* __restrict__ Ys,
                                       float* __restrict__ Ws,  // [2][16][KF]
                                       const float* __restrict__ W,
                                       const float* __restrict__ bias,
                                       bool relu) {
    const int t   = threadIdx.x;
    const int c0  = (t & 31) * 4;   // col group
    const int r0  = (t >> 5) * 8;   // row group

    unsigned long long acc[4][4];
    #pragma unroll
    for (int i = 0; i < 4; i++)
        #pragma unroll
        for (int j = 0; j < 4; j++) acc[i][j] = 0ull;

    // prefetch tile 0
    {
        uint32_t dst = (uint32_t)__cvta_generic_to_shared(Ws) + t * 16;
        cp_async16(dst, W + t * 4);
        cp_async16(dst + 256 * 16, W + (t + 256) * 4);
        cp_async_commit();
    }

    #pragma unroll 1
    for (int kt = 0; kt < 8; kt++) {
        __syncthreads();  // all threads done with tile kt-1 (buf (kt+1)&1 free)
        if (kt < 7) {
            const float* src = W + (kt + 1) * 16 * KF;
            uint32_t dst = (uint32_t)__cvta_generic_to_shared(
                               Ws + ((kt + 1) & 1) * 16 * KF) + t * 16;
            cp_async16(dst, src + t * 4);
            cp_async16(dst + 256 * 16, src + (t + 256) * 4);
            cp_async_commit();
            cp_async_wait<1>();
        } else {
            cp_async_wait<0>();
        }
        __syncthreads();  // tile kt visible to all

        const float* Wt = Ws + (kt & 1) * 16 * KF;
        #pragma unroll
        for (int kk = 0; kk < 16; kk++) {
            const int k = kt * 16 + kk;
            float4 w = *(const float4*)(Wt + kk * KF + c0);
            unsigned long long w2[4];
            w2[0] = dup_f32(w.x); w2[1] = dup_f32(w.y);
            w2[2] = dup_f32(w.z); w2[3] = dup_f32(w.w);
            ulonglong2 A0 = *(const ulonglong2*)(Xs + k * PAD + r0);
            ulonglong2 A1 = *(const ulonglong2*)(Xs + k * PAD + r0 + 4);
            unsigned long long ap[4] = {A0.x, A0.y, A1.x, A1.y};
            #pragma unroll
            for (int i = 0; i < 4; i++) {
                fma_f32x2(acc[i][0], ap[i], w2[0], acc[i][0]);
                fma_f32x2(acc[i][1], ap[i], w2[1], acc[i][1]);
                fma_f32x2(acc[i][2], ap[i], w2[2], acc[i][2]);
                fma_f32x2(acc[i][3], ap[i], w2[3], acc[i][3]);
            }
        }
    }

    float4 bv = *(const float4*)(bias + c0);
    float bb[4] = {bv.x, bv.y, bv.z, bv.w};
    #pragma unroll
    for (int j = 0; j < 4; j++) {
        float o[8];
        #pragma unroll
        for (int i = 0; i < 4; i++) {
            unpack_f32x2(o[2 * i], o[2 * i + 1], acc[i][j]);
        }
        #pragma unroll
        for (int i = 0; i < 8; i++) {
            float v = o[i] + bb[j];
            if (relu) v = fmaxf(v, 0.f);
            o[i] = v;
        }
        *(float4*)(Ys + (c0 + j) * PAD + r0)     = make_float4(o[0], o[1], o[2], o[3]);
        *(float4*)(Ys + (c0 + j) * PAD + r0 + 4) = make_float4(o[4], o[5], o[6], o[7]);
    }
}

// h = upd + mean over KNN rows within each cg group (in place, transposed buf)
__device__ __forceinline__ void add_mean(float* __restrict__ Ys) {
    const int t   = threadIdx.x;         // 256 = 128 feats * 2 groups
    const int c   = t >> 1;
    const int grp = t & 1;
    float* p = Ys + c * PAD + grp * KNN;
    float s = 0.f;
    #pragma unroll
    for (int i = 0; i < KNN; i++) s += p[i];
    s *= (1.0f / KNN);
    #pragma unroll
    for (int i = 0; i < KNN; i++) p[i] += s;
}

extern __shared__ float smem[];

__global__ __launch_bounds__(THREADS, 2)
void fused_kernel(const float* __restrict__ cg_xyz,
                  const float* __restrict__ mlp_W1, const float* __restrict__ mlp_b1,
                  const float* __restrict__ mlp_W2, const float* __restrict__ mlp_b2,
                  const float* __restrict__ upd_W1, const float* __restrict__ upd_b1,
                  const float* __restrict__ upd_W2, const float* __restrict__ upd_b2,
                  const float* __restrict__ dec_W1, const float* __restrict__ dec_b1) {
    float* bufA = smem;
    float* bufB = bufA + KF * PAD;
    float* dv   = bufB + KF * PAD;            // [MROWS][4]
    float* dist = dv + MROWS * 4;             // [MROWS]
    float* Ws   = dist + MROWS;               // [2][16][KF]

    const int t   = threadIdx.x;
    const int blk = blockIdx.x;               // B * NCG / CGS_PER_CTA = 2048
    const int b   = blk >> 7;
    const int cg0 = (blk & 127) * CGS_PER_CTA;

    // Phase 0: dist_vec + dist (row = cg_local*32 + j; neighbor = cg 1+j)
    if (t < MROWS) {
        const int cg = cg0 + (t / KNN);
        const int j  = t % KNN;
        const float* pj = cg_xyz + (size_t)(b * NCG + 1 + j) * 3;
        const float* pc = cg_xyz + (size_t)(b * NCG + cg) * 3;
        float d0 = pj[0] - pc[0], d1 = pj[1] - pc[1], d2 = pj[2] - pc[2];
        dv[t * 4 + 0] = d0; dv[t * 4 + 1] = d1; dv[t * 4 + 2] = d2;
        dist[t] = sqrtf(d0 * d0 + d1 * d1 + d2 * d2);
    }
    __syncthreads();

    // RBF expansion into bufA (transposed [k][r])
    const float delta = 10.0f / 127.0f;
    const float coeff = -0.5f / (delta * delta);
    for (int idx = t; idx < KF * MROWS; idx += THREADS) {
        const int k = idx / MROWS, r = idx % MROWS;
        const float x = dist[r] - (float)k * delta;
        bufA[k * PAD + r] = expf(coeff * x * x);
    }

    float* X = bufA;
    float* Y = bufB;
    for (int d = 0; d < DEPTH; d++) {
        const size_t wo = (size_t)d * KF * KF;
        const size_t bo = (size_t)d * KF;
        gemm64(X, Y, Ws, mlp_W1 + wo, mlp_b1 + bo, true);
        gemm64(Y, X, Ws, mlp_W2 + wo, mlp_b2 + bo, false);
        __syncthreads();
        add_mean(X);
        gemm64(X, Y, Ws, upd_W1 + wo, upd_b1 + bo, true);
        gemm64(Y, X, Ws, upd_W2 + wo, upd_b2 + bo, false);
    }
    gemm64(X, Y, Ws, dec_W1, dec_b1, true);   // Y = F (transposed)
    __syncthreads();

    // G[b][k][n] += sum_r F[k][r] * dv[r][n];  S[b][n] += sum_r dv[r][n]
    for (int p = t; p < KF * 3; p += THREADS) {
        const int k = p / 3, n = p % 3;
        const float* Fk = Y + k * PAD;
        float s = 0.f;
        #pragma unroll 8
        for (int r = 0; r < MROWS; r++) s = fmaf(Fk[r], dv[r * 4 + n], s);
        atomicAdd(&g_G[(b * KF + k) * 3 + n], s);
    }
    if (t < 3) {
        float s = 0.f;
        for (int r = 0; r < MROWS; r++) s += dv[r * 4 + t];
        atomicAdd(&g_S[b * 3 + t], s);
    }
}

// ---------------- dx_recon = G @ dec_W2 + dec_b2 * S ----------------
__global__ void dx_kernel(const float* __restrict__ dec_W2,
                          const float* __restrict__ dec_b2) {
    __shared__ float Gs[KF * 3];
    __shared__ float Ss[3];
    const int b = blockIdx.x >> 2;
    const int o = ((blockIdx.x & 3) << 8) + threadIdx.x;
    for (int i = threadIdx.x; i < KF * 3; i += 256) Gs[i] = g_G[b * KF * 3 + i];
    if (threadIdx.x < 3) Ss[threadIdx.x] = g_S[b * 3 + threadIdx.x];
    __syncthreads();
    float d0 = 0.f, d1 = 0.f, d2 = 0.f;
    #pragma unroll 4
    for (int k = 0; k < KF; k++) {
        const float w = dec_W2[k * NATOMS + o];
        d0 = fmaf(Gs[k * 3 + 0], w, d0);
        d1 = fmaf(Gs[k * 3 + 1], w, d1);
        d2 = fmaf(Gs[k * 3 + 2], w, d2);
    }
    const float bb = dec_b2[o];
    d0 += bb * Ss[0]; d1 += bb * Ss[1]; d2 += bb * Ss[2];
    float* p = g_dx + (size_t)(b * NATOMS + o) * 3;
    p[0] = d0; p[1] = d1; p[2] = d2;
}

// ---------------- cg_offset[b][j][n] = sum_o dx[b][o][n] * assign_norm[b][o][j] ----------------
__global__ void cgoff_kernel(const float* __restrict__ assign_norm) {
    __shared__ float dxs[256 * 3];
    const int b  = blockIdx.x >> 2;
    const int oc = blockIdx.x & 3;
    const int j  = threadIdx.x;
    const int obase = oc * 256;
    for (int i = threadIdx.x; i < 256 * 3; i += 256)
        dxs[i] = g_dx[(size_t)(b * NATOMS + obase) * 3 + i];
    __syncthreads();
    float a0 = 0.f, a1 = 0.f, a2 = 0.f;
    for (int oo = 0; oo < 256; oo++) {
        const float an = assign_norm[((size_t)b * NATOMS + obase + oo) * NCG + j];
        a0 = fmaf(an, dxs[oo * 3 + 0], a0);
        a1 = fmaf(an, dxs[oo * 3 + 1], a1);
        a2 = fmaf(an, dxs[oo * 3 + 2], a2);
    }
    atomicAdd(&g_cgoff[(b * NCG + j) * 3 + 0], a0);
    atomicAdd(&g_cgoff[(b * NCG + j) * 3 + 1], a1);
    atomicAdd(&g_cgoff[(b * NCG + j) * 3 + 2], a2);
}

// ---------------- xyz_recon = cg_xyz[idx] - cg_offset[idx] + dx ----------------
__global__ void recon_kernel(const float* __restrict__ cg_xyz,
                             const int* __restrict__ assign_idx,
                             float* __restrict__ out) {
    const int i = blockIdx.x * blockDim.x + threadIdx.x;
    if (i >= BB * NATOMS) return;
    const int b = i >> 10;
    const int o = i & 1023;
    const int ai = assign_idx[o];
    const float* cx = cg_xyz + (size_t)(b * NCG + ai) * 3;
    const float* co = g_cgoff + (size_t)(b * NCG + ai) * 3;
    const float* dx = g_dx + (size_t)i * 3;
    float* po = out + (size_t)BB * NATOMS * NCG + (size_t)BB * NATOMS * 3 + (size_t)i * 3;
    po[0] = cx[0] - co[0] + dx[0];
    po[1] = cx[1] - co[1] + dx[1];
    po[2] = cx[2] - co[2] + dx[2];
}

// ---------------- launch ----------------
extern "C" void kernel_launch(void* const* d_in, const int* in_sizes, int n_in,
                              void* d_out, int out_size) {
    const float* soft_assign = (const float*)d_in[0];
    const float* xyz         = (const float*)d_in[1];
    const float* cg_xyz      = (const float*)d_in[2];
    const float* assign_norm = (const float*)d_in[3];
    const int*   assign_idx  = (const int*)d_in[4];
    const float* mlp_W1 = (const float*)d_in[5];
    const float* mlp_b1 = (const float*)d_in[6];
    const float* mlp_W2 = (const float*)d_in[7];
    const float* mlp_b2 = (const float*)d_in[8];
    const float* upd_W1 = (const float*)d_in[9];
    const float* upd_b1 = (const float*)d_in[10];
    const float* upd_W2 = (const float*)d_in[11];
    const float* upd_b2 = (const float*)d_in[12];
    const float* dec_W1 = (const float*)d_in[13];
    const float* dec_b1 = (const float*)d_in[14];
    const float* dec_W2 = (const float*)d_in[15];
    const float* dec_b2 = (const float*)d_in[16];

    float* out = (float*)d_out;

    cudaMemcpyAsync(out, soft_assign, (size_t)BB * NATOMS * NCG * sizeof(float),
                    cudaMemcpyDeviceToDevice);
    cudaMemcpyAsync(out + (size_t)BB * NATOMS * NCG, xyz,
                    (size_t)BB * NATOMS * 3 * sizeof(float), cudaMemcpyDeviceToDevice);

    zero_kernel<<<32, 256>>>();

    cudaFuncSetAttribute(fused_kernel, cudaFuncAttributeMaxDynamicSharedMemorySize,
                         SMEM_BYTES);
    fused_kernel<<<BB * NCG / CGS_PER_CTA, THREADS, SMEM_BYTES>>>(
        cg_xyz, mlp_W1, mlp_b1, mlp_W2, mlp_b2,
        upd_W1, upd_b1, upd_W2, upd_b2, dec_W1, dec_b1);

    dx_kernel<<<BB * 4, 256>>>(dec_W2, dec_b2);
    cgoff_kernel<<<BB * 4, 256>>>(assign_norm);
    recon_kernel<<<(BB * NATOMS + 255) / 256, 256>>>(cg_xyz, assign_idx, out);
}

// round 4
// speedup vs baseline: 2.6051x; 2.3348x over previous
#include <cuda_runtime.h>
#include <cuda_bf16.h>
#include <math.h>
#include <stdint.h>

// Problem constants
#define BB      16
#define NCG     256
#define NATOMS  1024
#define KNN     32
#define KF      128
#define NLAYER  13

#define CGS_PER_CTA 4
#define ROWS    128
#define THREADS 256

// padded bf16 row stride (136 bf16 = 272 B)
#define LDX     136
#define MATB    34816          // 128*136*2 bytes per bf16 matrix
#define MATU32  8704           // 128*68 u32 per matrix

// ---- smem byte offsets ----
#define OFF_XHI   0
#define OFF_XLO   34816
#define OFF_W     69632        // [2 buf][hi+lo] = 2*69632
#define OFF_DV    208896       // 128*4 f32
#define OFF_DIST  210944       // 128 f32
#define OFF_BIAS  211456       // 13*128 f32 = 6656
#define SMEM_TOTAL 218112

// -------- device scratch (no allocs) --------
__device__ __align__(16) uint32_t g_Wbf[NLAYER * 2 * MATU32]; // [layer][hi/lo][128][68]
__device__ float g_bias[NLAYER * KF];
__device__ float g_G[BB * KF * 3];
__device__ float g_S[BB * 3];
__device__ float g_dx[BB * NATOMS * 3];
__device__ float g_cgoff[BB * NCG * 3];

// ---------------- helpers ----------------
__device__ __forceinline__ uint32_t smem_u32(const void* p) {
    uint32_t a;
    asm("{ .reg .u64 t; cvta.to.shared.u64 t, %1; cvt.u32.u64 %0, t; }"
        : "=r"(a) : "l"(p));
    return a;
}
// pack (e0, e1) -> bf16x2 with e0 in LOW half
__device__ __forceinline__ uint32_t pack_bf16x2(float e0, float e1) {
    uint32_t r;
    asm("cvt.rn.bf16x2.f32 %0, %1, %2;" : "=r"(r) : "f"(e1), "f"(e0));
    return r;
}
__device__ __forceinline__ void split2(float w0, float w1, uint32_t& h2, uint32_t& l2) {
    h2 = pack_bf16x2(w0, w1);
    float hf0 = __uint_as_float(h2 << 16);
    float hf1 = __uint_as_float(h2 & 0xffff0000u);
    l2 = pack_bf16x2(w0 - hf0, w1 - hf1);
}
__device__ __forceinline__ void cp_async16(uint32_t smem_addr, const void* gptr) {
    asm volatile("cp.async.cg.shared.global [%0], [%1], 16;"
                 :: "r"(smem_addr), "l"(gptr));
}
__device__ __forceinline__ void cp_async_commit() {
    asm volatile("cp.async.commit_group;");
}
template <int N>
__device__ __forceinline__ void cp_async_wait() {
    asm volatile("cp.async.wait_group %0;" :: "n"(N));
}
__device__ __forceinline__ void ldsm_x4(uint32_t* r, uint32_t addr) {
    asm volatile("ldmatrix.sync.aligned.m8n8.x4.shared.b16 {%0,%1,%2,%3}, [%4];"
                 : "=r"(r[0]), "=r"(r[1]), "=r"(r[2]), "=r"(r[3]) : "r"(addr));
}
__device__ __forceinline__ void ldsm_x4_t(uint32_t* r, uint32_t addr) {
    asm volatile("ldmatrix.sync.aligned.m8n8.x4.trans.shared.b16 {%0,%1,%2,%3}, [%4];"
                 : "=r"(r[0]), "=r"(r[1]), "=r"(r[2]), "=r"(r[3]) : "r"(addr));
}
__device__ __forceinline__ void mma_bf16(float* d, const uint32_t* a, const uint32_t* b) {
    asm volatile(
        "mma.sync.aligned.m16n8k16.row.col.f32.bf16.bf16.f32 "
        "{%0,%1,%2,%3},{%4,%5,%6,%7},{%8,%9},{%0,%1,%2,%3};"
        : "+f"(d[0]), "+f"(d[1]), "+f"(d[2]), "+f"(d[3])
        : "r"(a[0]), "r"(a[1]), "r"(a[2]), "r"(a[3]), "r"(b[0]), "r"(b[1]));
}

// ---------------- zero scratch ----------------
__global__ void zero_kernel() {
    const int n1 = BB * KF * 3, n2 = BB * 3, n3 = BB * NCG * 3;
    const int total = n1 + n2 + n3;
    for (int i = blockIdx.x * blockDim.x + threadIdx.x; i < total;
         i += gridDim.x * blockDim.x) {
        if (i < n1)            g_G[i] = 0.f;
        else if (i < n1 + n2)  g_S[i - n1] = 0.f;
        else                   g_cgoff[i - n1 - n2] = 0.f;
    }
}

// ---------------- prologue: fp32 weights -> bf16 hi/lo (padded) ----------------
__device__ __forceinline__ const float* layer_W(
    int d, const float* mW1, const float* mW2, const float* uW1,
    const float* uW2, const float* dW1) {
    if (d == 12) return dW1;
    const int g = d >> 2, ty = d & 3;
    const size_t o = (size_t)g * KF * KF;
    if (ty == 0) return mW1 + o;
    if (ty == 1) return mW2 + o;
    if (ty == 2) return uW1 + o;
    return uW2 + o;
}
__device__ __forceinline__ const float* layer_b(
    int d, const float* mb1, const float* mb2, const float* ub1,
    const float* ub2, const float* db1) {
    if (d == 12) return db1;
    const int g = d >> 2, ty = d & 3;
    const size_t o = (size_t)g * KF;
    if (ty == 0) return mb1 + o;
    if (ty == 1) return mb2 + o;
    if (ty == 2) return ub1 + o;
    return ub2 + o;
}

#define NWPAIR (NLAYER * KF * 64)   // 106496 col-pairs

__global__ void convert_kernel(const float* mW1, const float* mb1,
                               const float* mW2, const float* mb2,
                               const float* uW1, const float* ub1,
                               const float* uW2, const float* ub2,
                               const float* dW1, const float* db1) {
    const int i = blockIdx.x * blockDim.x + threadIdx.x;
    if (i < NWPAIR) {
        const int d   = i / (KF * 64);
        const int rem = i % (KF * 64);
        const int k   = rem >> 6;
        const int cp  = rem & 63;
        const float* W = layer_W(d, mW1, mW2, uW1, uW2, dW1);
        const float2 w = *(const float2*)(W + (size_t)k * KF + 2 * cp);
        uint32_t h2, l2;
        split2(w.x, w.y, h2, l2);
        const int base = d * 2 * MATU32 + k * 68 + cp;
        g_Wbf[base]          = h2;
        g_Wbf[base + MATU32] = l2;
    } else if (i < NWPAIR + NLAYER * KF) {
        const int j = i - NWPAIR;
        const int d = j >> 7, c = j & 127;
        g_bias[j] = layer_b(d, mb1, mb2, ub1, ub2, db1)[c];
    }
}

// ---------------- fused MLP chain (mma.sync bf16, 3-pass split) ----------------
extern __shared__ __align__(16) char smem[];

__global__ __launch_bounds__(THREADS, 1)
void fused_kernel(const float* __restrict__ cg_xyz) {
    const uint32_t sb = smem_u32(smem);
    const int t = threadIdx.x, wid = t >> 5, lane = t & 31;
    const int wm = wid & 3;        // row group: rows [32wm, 32wm+32)
    const int wn = wid >> 2;       // col group: cols [64wn, 64wn+64)
    const int r16 = lane & 15, c8 = (lane >> 4) << 3;
    const int tig = lane & 3, grp = lane >> 2;

    const int blk = blockIdx.x;
    const int b   = blk >> 6;
    const int cg0 = (blk & 63) * CGS_PER_CTA;

    float* dv   = (float*)(smem + OFF_DV);
    float* dist = (float*)(smem + OFF_DIST);
    float* bias = (float*)(smem + OFF_BIAS);

    // phase 0: dv / dist
    if (t < ROWS) {
        const int cg = cg0 + (t >> 5);
        const int j  = t & 31;
        const float* pj = cg_xyz + (size_t)(b * NCG + 1 + j) * 3;
        const float* pc = cg_xyz + (size_t)(b * NCG + cg) * 3;
        float d0 = pj[0] - pc[0], d1 = pj[1] - pc[1], d2 = pj[2] - pc[2];
        dv[t*4+0] = d0; dv[t*4+1] = d1; dv[t*4+2] = d2; dv[t*4+3] = 0.f;
        dist[t] = sqrtf(d0*d0 + d1*d1 + d2*d2);
    }
    // bias preload
    for (int i = t; i < NLAYER * KF; i += THREADS) bias[i] = g_bias[i];

    // prefetch W layer 0 into buf 0
    for (int i = t; i < 2 * MATU32 / 4; i += THREADS)
        cp_async16(sb + OFF_W + i * 16, g_Wbf + i * 4);
    cp_async_commit();

    __syncthreads();

    // RBF expansion -> Xhi/Xlo
    {
        const float delta = 10.0f / 127.0f;
        const float coeff = -0.5f / (delta * delta);
        const int row = t >> 1, half = (t & 1) * 64;
        const float dr = dist[row];
        uint32_t* xh = (uint32_t*)(smem + OFF_XHI) + (row * LDX + half) / 2;
        uint32_t* xl = (uint32_t*)(smem + OFF_XLO) + (row * LDX + half) / 2;
        #pragma unroll 8
        for (int j = 0; j < 32; j++) {
            const int col = half + 2 * j;
            const float x0 = dr - (float)col * delta;
            const float x1 = dr - (float)(col + 1) * delta;
            uint32_t h2, l2;
            split2(expf(coeff * x0 * x0), expf(coeff * x1 * x1), h2, l2);
            xh[j] = h2;
            xl[j] = l2;
        }
    }
    cp_async_wait<0>();
    __syncthreads();

    for (int d = 0; d < NLAYER; d++) {
        // prefetch next layer's weights into the other buffer
        if (d + 1 < NLAYER) {
            const uint32_t* src = g_Wbf + (d + 1) * 2 * MATU32;
            const uint32_t dst = sb + OFF_W + ((d + 1) & 1) * (2 * MATB);
            for (int i = t; i < 2 * MATU32 / 4; i += THREADS)
                cp_async16(dst + i * 16, src + i * 4);
            cp_async_commit();
        }

        const uint32_t whi = sb + OFF_W + (d & 1) * (2 * MATB);
        const uint32_t wlo = whi + MATB;

        float acc[2][8][4];
        #pragma unroll
        for (int mt = 0; mt < 2; mt++)
            #pragma unroll
            for (int nt = 0; nt < 8; nt++)
                #pragma unroll
                for (int q = 0; q < 4; q++) acc[mt][nt][q] = 0.f;

        #pragma unroll 1
        for (int kk = 0; kk < 8; kk++) {
            const int k0 = kk * 16;
            uint32_t ah[2][4], al[2][4];
            #pragma unroll
            for (int mt = 0; mt < 2; mt++) {
                const int row = wm * 32 + mt * 16 + r16;
                const uint32_t off = (uint32_t)(row * LDX + k0 + c8) * 2;
                ldsm_x4(ah[mt], sb + OFF_XHI + off);
                ldsm_x4(al[mt], sb + OFF_XLO + off);
            }
            uint32_t bh[4][4], bl[4][4];
            #pragma unroll
            for (int ng = 0; ng < 4; ng++) {
                const int nn = wn * 64 + ng * 16;
                const uint32_t off = (uint32_t)((k0 + r16) * LDX + nn + c8) * 2;
                ldsm_x4_t(bh[ng], whi + off);
                ldsm_x4_t(bl[ng], wlo + off);
            }
            #pragma unroll
            for (int mt = 0; mt < 2; mt++)
                #pragma unroll
                for (int ng = 0; ng < 4; ng++) {
                    mma_bf16(acc[mt][2*ng],   ah[mt], &bh[ng][0]);
                    mma_bf16(acc[mt][2*ng+1], ah[mt], &bh[ng][2]);
                    mma_bf16(acc[mt][2*ng],   ah[mt], &bl[ng][0]);
                    mma_bf16(acc[mt][2*ng+1], ah[mt], &bl[ng][2]);
                    mma_bf16(acc[mt][2*ng],   al[mt], &bh[ng][0]);
                    mma_bf16(acc[mt][2*ng+1], al[mt], &bh[ng][2]);
                }
        }

        // bias + relu
        const bool relu   = ((d & 1) == 0);
        const bool domean = (d < 12) && ((d & 3) == 1);
        const float* bl_ = bias + d * KF;
        #pragma unroll
        for (int nt = 0; nt < 8; nt++) {
            const int col = wn * 64 + nt * 8 + tig * 2;
            const float b0 = bl_[col], b1 = bl_[col + 1];
            #pragma unroll
            for (int mt = 0; mt < 2; mt++) {
                acc[mt][nt][0] += b0; acc[mt][nt][1] += b1;
                acc[mt][nt][2] += b0; acc[mt][nt][3] += b1;
                if (relu) {
                    acc[mt][nt][0] = fmaxf(acc[mt][nt][0], 0.f);
                    acc[mt][nt][1] = fmaxf(acc[mt][nt][1], 0.f);
                    acc[mt][nt][2] = fmaxf(acc[mt][nt][2], 0.f);
                    acc[mt][nt][3] = fmaxf(acc[mt][nt][3], 0.f);
                }
            }
        }
        // KNN-mean (rows of this warp = one cg group)
        if (domean) {
            #pragma unroll
            for (int nt = 0; nt < 8; nt++) {
                float s0 = acc[0][nt][0] + acc[0][nt][2] + acc[1][nt][0] + acc[1][nt][2];
                float s1 = acc[0][nt][1] + acc[0][nt][3] + acc[1][nt][1] + acc[1][nt][3];
                #pragma unroll
                for (int m = 4; m <= 16; m <<= 1) {
                    s0 += __shfl_xor_sync(0xffffffffu, s0, m);
                    s1 += __shfl_xor_sync(0xffffffffu, s1, m);
                }
                s0 *= (1.0f / 32.0f);
                s1 *= (1.0f / 32.0f);
                #pragma unroll
                for (int mt = 0; mt < 2; mt++) {
                    acc[mt][nt][0] += s0; acc[mt][nt][2] += s0;
                    acc[mt][nt][1] += s1; acc[mt][nt][3] += s1;
                }
            }
        }

        __syncthreads();   // all warps done reading X

        if (d < 12) {
            // write activations back (hi/lo split)
            #pragma unroll
            for (int mt = 0; mt < 2; mt++) {
                const int row0 = wm * 32 + mt * 16 + grp;
                #pragma unroll
                for (int nt = 0; nt < 8; nt++) {
                    const int col = wn * 64 + nt * 8 + tig * 2;
                    uint32_t h2, l2;
                    split2(acc[mt][nt][0], acc[mt][nt][1], h2, l2);
                    const uint32_t o0 = (uint32_t)(row0 * LDX + col) * 2;
                    *(uint32_t*)(smem + OFF_XHI + o0) = h2;
                    *(uint32_t*)(smem + OFF_XLO + o0) = l2;
                    split2(acc[mt][nt][2], acc[mt][nt][3], h2, l2);
                    const uint32_t o1 = o0 + 8 * LDX * 2;
                    *(uint32_t*)(smem + OFF_XHI + o1) = h2;
                    *(uint32_t*)(smem + OFF_XLO + o1) = l2;
                }
            }
        } else {
            // G contraction: G[b][col][n] += sum_rows F[row][col] * dv[row][n]
            float dvc[2][2][3];
            #pragma unroll
            for (int mt = 0; mt < 2; mt++) {
                const int row0 = wm * 32 + mt * 16 + grp;
                #pragma unroll
                for (int h = 0; h < 2; h++) {
                    dvc[mt][h][0] = dv[(row0 + 8*h) * 4 + 0];
                    dvc[mt][h][1] = dv[(row0 + 8*h) * 4 + 1];
                    dvc[mt][h][2] = dv[(row0 + 8*h) * 4 + 2];
                }
            }
            #pragma unroll
            for (int nt = 0; nt < 8; nt++) {
                float g0[3] = {0.f, 0.f, 0.f}, g1[3] = {0.f, 0.f, 0.f};
                #pragma unroll
                for (int mt = 0; mt < 2; mt++)
                    #pragma unroll
                    for (int n = 0; n < 3; n++) {
                        g0[n] += acc[mt][nt][0] * dvc[mt][0][n]
                               + acc[mt][nt][2] * dvc[mt][1][n];
                        g1[n] += acc[mt][nt][1] * dvc[mt][0][n]
                               + acc[mt][nt][3] * dvc[mt][1][n];
                    }
                #pragma unroll
                for (int m = 4; m <= 16; m <<= 1)
                    #pragma unroll
                    for (int n = 0; n < 3; n++) {
                        g0[n] += __shfl_xor_sync(0xffffffffu, g0[n], m);
                        g1[n] += __shfl_xor_sync(0xffffffffu, g1[n], m);
                    }
                if (grp == 0) {
                    const int col = wn * 64 + nt * 8 + tig * 2;
                    float* gp = g_G + (size_t)(b * KF + col) * 3;
                    atomicAdd(gp + 0, g0[0]);
                    atomicAdd(gp + 1, g0[1]);
                    atomicAdd(gp + 2, g0[2]);
                    atomicAdd(gp + 3, g1[0]);
                    atomicAdd(gp + 4, g1[1]);
                    atomicAdd(gp + 5, g1[2]);
                }
            }
        }

        cp_async_wait<0>();
        __syncthreads();   // X writes visible; next-layer weights ready
    }

    if (t < 3) {
        float s = 0.f;
        for (int r = 0; r < ROWS; r++) s += dv[r * 4 + t];
        atomicAdd(&g_S[b * 3 + t], s);
    }
}

// ---------------- dx_recon = G @ dec_W2 + dec_b2 * S ----------------
__global__ void dx_kernel(const float* __restrict__ dec_W2,
                          const float* __restrict__ dec_b2) {
    __shared__ float Gs[KF * 3];
    __shared__ float Ss[3];
    const int b = blockIdx.x >> 2;
    const int o = ((blockIdx.x & 3) << 8) + threadIdx.x;
    for (int i = threadIdx.x; i < KF * 3; i += 256) Gs[i] = g_G[b * KF * 3 + i];
    if (threadIdx.x < 3) Ss[threadIdx.x] = g_S[b * 3 + threadIdx.x];
    __syncthreads();
    float d0 = 0.f, d1 = 0.f, d2 = 0.f;
    #pragma unroll 4
    for (int k = 0; k < KF; k++) {
        const float w = dec_W2[k * NATOMS + o];
        d0 = fmaf(Gs[k*3+0], w, d0);
        d1 = fmaf(Gs[k*3+1], w, d1);
        d2 = fmaf(Gs[k*3+2], w, d2);
    }
    const float bb = dec_b2[o];
    d0 += bb * Ss[0]; d1 += bb * Ss[1]; d2 += bb * Ss[2];
    float* p = g_dx + (size_t)(b * NATOMS + o) * 3;
    p[0] = d0; p[1] = d1; p[2] = d2;
}

// ---------------- cg_offset ----------------
__global__ void cgoff_kernel(const float* __restrict__ assign_norm) {
    __shared__ float dxs[64 * 3];
    const int b  = blockIdx.x >> 4;
    const int oc = blockIdx.x & 15;
    const int j  = threadIdx.x;
    const int obase = oc * 64;
    for (int i = threadIdx.x; i < 64 * 3; i += 256)
        dxs[i] = g_dx[(size_t)(b * NATOMS + obase) * 3 + i];
    __syncthreads();
    float a0 = 0.f, a1 = 0.f, a2 = 0.f;
    #pragma unroll 4
    for (int oo = 0; oo < 64; oo++) {
        const float an = assign_norm[((size_t)b * NATOMS + obase + oo) * NCG + j];
        a0 = fmaf(an, dxs[oo*3+0], a0);
        a1 = fmaf(an, dxs[oo*3+1], a1);
        a2 = fmaf(an, dxs[oo*3+2], a2);
    }
    atomicAdd(&g_cgoff[(b * NCG + j) * 3 + 0], a0);
    atomicAdd(&g_cgoff[(b * NCG + j) * 3 + 1], a1);
    atomicAdd(&g_cgoff[(b * NCG + j) * 3 + 2], a2);
}

// ---------------- xyz_recon ----------------
__global__ void recon_kernel(const float* __restrict__ cg_xyz,
                             const int* __restrict__ assign_idx,
                             float* __restrict__ out) {
    const int i = blockIdx.x * blockDim.x + threadIdx.x;
    if (i >= BB * NATOMS) return;
    const int b = i >> 10;
    const int o = i & 1023;
    const int ai = assign_idx[o];
    const float* cx = cg_xyz + (size_t)(b * NCG + ai) * 3;
    const float* co = g_cgoff + (size_t)(b * NCG + ai) * 3;
    const float* dx = g_dx + (size_t)i * 3;
    float* po = out + (size_t)BB * NATOMS * NCG + (size_t)BB * NATOMS * 3 + (size_t)i * 3;
    po[0] = cx[0] - co[0] + dx[0];
    po[1] = cx[1] - co[1] + dx[1];
    po[2] = cx[2] - co[2] + dx[2];
}

// ---------------- launch ----------------
extern "C" void kernel_launch(void* const* d_in, const int* in_sizes, int n_in,
                              void* d_out, int out_size) {
    const float* soft_assign = (const float*)d_in[0];
    const float* xyz         = (const float*)d_in[1];
    const float* cg_xyz      = (const float*)d_in[2];
    const float* assign_norm = (const float*)d_in[3];
    const int*   assign_idx  = (const int*)d_in[4];
    const float* mlp_W1 = (const float*)d_in[5];
    const float* mlp_b1 = (const float*)d_in[6];
    const float* mlp_W2 = (const float*)d_in[7];
    const float* mlp_b2 = (const float*)d_in[8];
    const float* upd_W1 = (const float*)d_in[9];
    const float* upd_b1 = (const float*)d_in[10];
    const float* upd_W2 = (const float*)d_in[11];
    const float* upd_b2 = (const float*)d_in[12];
    const float* dec_W1 = (const float*)d_in[13];
    const float* dec_b1 = (const float*)d_in[14];
    const float* dec_W2 = (const float*)d_in[15];
    const float* dec_b2 = (const float*)d_in[16];

    float* out = (float*)d_out;

    cudaMemcpyAsync(out, soft_assign, (size_t)BB * NATOMS * NCG * sizeof(float),
                    cudaMemcpyDeviceToDevice);
    cudaMemcpyAsync(out + (size_t)BB * NATOMS * NCG, xyz,
                    (size_t)BB * NATOMS * 3 * sizeof(float), cudaMemcpyDeviceToDevice);

    zero_kernel<<<32, 256>>>();
    convert_kernel<<<(NWPAIR + NLAYER * KF + 255) / 256, 256>>>(
        mlp_W1, mlp_b1, mlp_W2, mlp_b2,
        upd_W1, upd_b1, upd_W2, upd_b2, dec_W1, dec_b1);

    cudaFuncSetAttribute(fused_kernel, cudaFuncAttributeMaxDynamicSharedMemorySize,
                         SMEM_TOTAL);
    fused_kernel<<<BB * NCG / CGS_PER_CTA, THREADS, SMEM_TOTAL>>>(cg_xyz);

    dx_kernel<<<BB * 4, 256>>>(dec_W2, dec_b2);
    cgoff_kernel<<<BB * 16, 256>>>(assign_norm);
    recon_kernel<<<(BB * NATOMS + 255) / 256, 256>>>(cg_xyz, assign_idx, out);
}